// round 15
// baseline (speedup 1.0000x reference)
#include <cuda_runtime.h>
#include <stdint.h>

// ---------------------------------------------------------------------------
// BoltzmannGateSTE: keep top-k (k = int(n/e)) by |x|, zero the rest.
// R15 = R14 (59.4us; fused_p1 45.0us @ 61% DRAM) + occupancy quantization:
//   fused_p1 grid 1024 -> 1184 (148 SMs x 8, integral waves; occ 83.5->~100)
//   fix_clean grid 256 -> 148 (less launch ramp, same work)
//   K1 fused_p1: stream read -> speculative write; stage window
//      [0.8984375, 0.90234375) elems to list + 2^16 hist + padded supers;
//      LAST block (ticket) verifies AND resolves exact tbits in-kernel.
//   K2 fb_all (grid 148): cold exact 3-level radix select + re-mask + clean.
//   K3 fix_clean (grid 148, tiny code image): scatter-fix keepers + zero
//      dirty bins from list; last block resets scalars (replay-pristine).
// ---------------------------------------------------------------------------

#define NBINS   (1u << 16)     // fine bins over the window (1 ulp each)
#define NSUP    256            // supers of 256 bins
#define SUPSTR  32             // super stride in uints (128B anti-contention)
#define NCOARSE 4096
#define LISTCAP (1 << 20)      // 1M entries (expected ~70K)
#define CAPB    512            // per-block staging (expected ~59/block)
#define GRID    1184           // 148 SMs * 8 — integral waves
#define BLK     256
#define STRIDE  (GRID * BLK)
#define FBGRID  148
#define FIXGRID 148
#define WLO_N   0x3F660000u    // bits(0.8984375f)
#define WSPAN_N (1u << 16)
#define WHI_N   (WLO_N + WSPAN_N)   // bits(0.90234375f)

__device__ __align__(16) unsigned g_fine[NBINS];
__device__ unsigned g_superp[NSUP * SUPSTR];   // padded supers
__device__ unsigned g_coarse[NCOARSE];         // fallback only
__device__ unsigned g_h2[8];                   // fallback only
__device__ unsigned g_A;
__device__ unsigned g_listcnt;
__device__ unsigned g_overflow;
__device__ unsigned g_mode;
__device__ unsigned g_tbits;
__device__ unsigned g_sel;         // fallback scan outputs
__device__ unsigned g_rem2;
__device__ unsigned g_done1;       // K1 ticket
__device__ unsigned g_done2;       // K3 ticket
__device__ unsigned g_fb_cnt;      // fallback grid barrier
__device__ volatile unsigned g_fb_sense;
__device__ uint2    g_list[LISTCAP];

// ---------------- K1: fused stream + last-block verify & resolve -----------
__global__ void __launch_bounds__(BLK)
fused_p1(const float4* __restrict__ x, float4* __restrict__ out,
         int n4, int rem, unsigned k)
{
    __shared__ uint2 sbuf[CAPB];          // 4KB staging
    __shared__ unsigned scratch[BLK];     // 1KB reduce/scan
    __shared__ unsigned svar[6];          // 0:scnt 1:sbase 2:sb 3:krem2 4:last 5:mode
    const int tid = threadIdx.x;
    const int gtid = blockIdx.x * BLK + tid;
    const float* xs = (const float*)x;
    float* outs = (float*)out;

    if (tid == 0) svar[0] = 0;
    __syncthreads();

    unsigned cntHi = 0;
#define DO1(f, eidx, odst) { \
    unsigned raw = __float_as_uint(f); \
    unsigned u = raw & 0x7FFFFFFFu; \
    odst = (u >= WHI_N) ? f : 0.0f; \
    cntHi += (u >= WHI_N); \
    if (u - WLO_N < WSPAN_N) { \
        unsigned p = atomicAdd(&svar[0], 1u); \
        if (p < CAPB) { sbuf[p].x = (eidx); sbuf[p].y = raw; } \
    } \
}
#define DO4(vv, fi) { \
    float4 o; \
    unsigned eb = (unsigned)(fi) * 4u; \
    DO1(vv.x, eb + 0u, o.x); \
    DO1(vv.y, eb + 1u, o.y); \
    DO1(vv.z, eb + 2u, o.z); \
    DO1(vv.w, eb + 3u, o.w); \
    __stcs(&out[fi], o); \
}
    {
        int i = gtid;
        for (; i + STRIDE < n4; i += 2 * STRIDE) {
            float4 v0 = __ldcs(&x[i]);
            float4 v1 = __ldcs(&x[i + STRIDE]);
            DO4(v0, i);
            DO4(v1, i + STRIDE);
        }
        for (; i < n4; i += STRIDE) {
            float4 v = __ldcs(&x[i]);
            DO4(v, i);
        }
    }
#undef DO4
#undef DO1
    if (gtid < rem) {   // scalar tail
        float f = xs[n4 * 4 + gtid];
        unsigned raw = __float_as_uint(f);
        unsigned u = raw & 0x7FFFFFFFu;
        cntHi += (u >= WHI_N);
        outs[n4 * 4 + gtid] = (u >= WHI_N) ? f : 0.0f;
        if (u - WLO_N < WSPAN_N) {
            unsigned p = atomicAdd(&svar[0], 1u);
            if (p < CAPB) { sbuf[p].x = (unsigned)(n4 * 4 + gtid); sbuf[p].y = raw; }
        }
    }

    // block-reduce cntHi; reserve list space
    scratch[tid] = cntHi;
    __syncthreads();
    for (int off = BLK / 2; off > 0; off >>= 1) {
        if (tid < off) scratch[tid] += scratch[tid + off];
        __syncthreads();
    }
    if (tid == 0) {
        if (scratch[0]) atomicAdd(&g_A, scratch[0]);
        unsigned c = svar[0];
        if (c > CAPB) { c = CAPB; g_overflow = 1u; }
        unsigned base = atomicAdd(&g_listcnt, c);
        if (base + c > LISTCAP) g_overflow = 1u;
        svar[0] = c;
        svar[1] = base;
    }
    __syncthreads();
    {   // flush staging -> list + fine hist + padded supers
        unsigned c = svar[0], base = svar[1];
        for (unsigned j = tid; j < c; j += BLK) {
            uint2 e = sbuf[j];
            if (base + j < LISTCAP) g_list[base + j] = e;
            unsigned d = (e.y & 0x7FFFFFFFu) - WLO_N;
            atomicAdd(&g_fine[d], 1u);
            atomicAdd(&g_superp[(d >> 8) * SUPSTR], 1u);
        }
    }

    // ---- last block: verify + resolve exact tbits -------------------------
    __syncthreads();
    __threadfence();
    if (tid == 0) svar[4] = (atomicAdd(&g_done1, 1u) == GRID - 1u) ? 1u : 0u;
    __syncthreads();
    if (!svar[4]) return;
    __threadfence();

    if (tid == 0) {
        unsigned A = g_A, cnt = g_listcnt, ov = g_overflow;
        unsigned mode = 1u, krem = 0u;
        if (!ov && A < k && (k - A) <= cnt) { mode = 0u; krem = k - A; }
        g_mode = mode;
        svar[5] = mode;
        svar[3] = krem;
    }
    __syncthreads();
    if (svar[5]) return;            // fallback kernel will handle it
    const unsigned krem = svar[3];

    // scan 256 supers (descending rank)
    unsigned c = g_superp[tid * SUPSTR];
    scratch[tid] = c;
    __syncthreads();
    for (int off = 1; off < BLK; off <<= 1) {
        unsigned add = (tid + off < BLK) ? scratch[tid + off] : 0u;
        __syncthreads();
        scratch[tid] += add;
        __syncthreads();
    }
    {
        unsigned above = (tid < BLK - 1) ? scratch[tid + 1] : 0u;
        if (above < krem && above + c >= krem) { svar[2] = (unsigned)tid; svar[3] = krem - above; }
    }
    __syncthreads();
    const unsigned sb = svar[2], krem2 = svar[3];

    // scan the 256 fine bins of super sb
    unsigned c2 = g_fine[sb * 256u + tid];
    __syncthreads();
    scratch[tid] = c2;
    __syncthreads();
    for (int off = 1; off < BLK; off <<= 1) {
        unsigned add = (tid + off < BLK) ? scratch[tid + off] : 0u;
        __syncthreads();
        scratch[tid] += add;
        __syncthreads();
    }
    {
        unsigned above = (tid < BLK - 1) ? scratch[tid + 1] : 0u;
        if (above < krem2 && above + c2 >= krem2)
            g_tbits = WLO_N + sb * 256u + (unsigned)tid;
    }
}

// ---------------- K2: cold exact fallback (no-op when verify passed) -------
__device__ __forceinline__ void fb_bar() {
    __syncthreads();
    if (threadIdx.x == 0) {
        unsigned s = g_fb_sense ^ 1u;
        __threadfence();
        if (atomicAdd(&g_fb_cnt, 1u) == FBGRID - 1u) {
            g_fb_cnt = 0u;
            __threadfence();
            g_fb_sense = s;
        } else {
            while (g_fb_sense != s) __nanosleep(64);
            __threadfence();
        }
    }
    __syncthreads();
}

__global__ void __launch_bounds__(BLK)
fb_all(const float4* __restrict__ x, float4* __restrict__ out,
       int n4, int rem, unsigned k)
{
    if (g_mode == 0u) return;      // normal path handled elsewhere
    __shared__ unsigned scratch[BLK];
    const int tid = threadIdx.x;
    const int gtid = blockIdx.x * BLK + tid;
    const int FTOT = FBGRID * BLK;
    const float* xs = (const float*)x;
    float* outs = (float*)out;

    // zero stale scratch dirtied by the normal flush
    for (unsigned i = gtid; i < NBINS; i += FTOT) g_fine[i] = 0;
    for (int i = gtid; i < NSUP * SUPSTR; i += FTOT) g_superp[i] = 0;
    if (gtid < 8) g_h2[gtid] = 0;
    fb_bar();

    // level 1: coarse hist (4096 bins of 2^19)
    for (int i = gtid; i < n4; i += FTOT) {
        float4 v = x[i];
        atomicAdd(&g_coarse[(__float_as_uint(v.x) & 0x7FFFFFFFu) >> 19], 1u);
        atomicAdd(&g_coarse[(__float_as_uint(v.y) & 0x7FFFFFFFu) >> 19], 1u);
        atomicAdd(&g_coarse[(__float_as_uint(v.z) & 0x7FFFFFFFu) >> 19], 1u);
        atomicAdd(&g_coarse[(__float_as_uint(v.w) & 0x7FFFFFFFu) >> 19], 1u);
    }
    for (int g = gtid; g < rem; g += FTOT)
        atomicAdd(&g_coarse[(__float_as_uint(xs[n4 * 4 + g]) & 0x7FFFFFFFu) >> 19], 1u);
    fb_bar();

    if (blockIdx.x == 0) {   // scan 4096: 16 per thread
        unsigned c[16], sum = 0;
        #pragma unroll
        for (int j = 0; j < 16; j++) { c[j] = g_coarse[tid * 16 + j]; sum += c[j]; }
        scratch[tid] = sum;
        __syncthreads();
        for (int off = 1; off < BLK; off <<= 1) {
            unsigned add = (tid + off < BLK) ? scratch[tid + off] : 0u;
            __syncthreads();
            scratch[tid] += add;
            __syncthreads();
        }
        unsigned cum = (tid < BLK - 1) ? scratch[tid + 1] : 0u;
        #pragma unroll
        for (int j = 15; j >= 0; j--) {
            unsigned prev = cum;
            cum += c[j];
            if (cum >= k && prev < k) { g_sel = (unsigned)(tid * 16 + j); g_rem2 = k - prev; }
        }
    }
    fb_bar();
    const unsigned base0 = g_sel << 19;
    const unsigned krem1 = g_rem2;

    // level 2: 2^16 bins of width 8
    for (int i = gtid; i < n4; i += FTOT) {
        float4 v = x[i];
        unsigned u0 = __float_as_uint(v.x) & 0x7FFFFFFFu;
        unsigned u1 = __float_as_uint(v.y) & 0x7FFFFFFFu;
        unsigned u2 = __float_as_uint(v.z) & 0x7FFFFFFFu;
        unsigned u3 = __float_as_uint(v.w) & 0x7FFFFFFFu;
        if (u0 - base0 < (1u << 19)) atomicAdd(&g_fine[(u0 - base0) >> 3], 1u);
        if (u1 - base0 < (1u << 19)) atomicAdd(&g_fine[(u1 - base0) >> 3], 1u);
        if (u2 - base0 < (1u << 19)) atomicAdd(&g_fine[(u2 - base0) >> 3], 1u);
        if (u3 - base0 < (1u << 19)) atomicAdd(&g_fine[(u3 - base0) >> 3], 1u);
    }
    for (int g = gtid; g < rem; g += FTOT) {
        unsigned u = __float_as_uint(xs[n4 * 4 + g]) & 0x7FFFFFFFu;
        if (u - base0 < (1u << 19)) atomicAdd(&g_fine[(u - base0) >> 3], 1u);
    }
    fb_bar();

    if (blockIdx.x == 0) {   // scan 65536: 256 per thread (cold path)
        unsigned sum = 0;
        for (int j = 0; j < 256; j++) sum += g_fine[tid * 256 + j];
        scratch[tid] = sum;
        __syncthreads();
        for (int off = 1; off < BLK; off <<= 1) {
            unsigned add = (tid + off < BLK) ? scratch[tid + off] : 0u;
            __syncthreads();
            scratch[tid] += add;
            __syncthreads();
        }
        unsigned above = (tid < BLK - 1) ? scratch[tid + 1] : 0u;
        if (above < krem1 && above + sum >= krem1) {
            unsigned cum = above;
            for (int j = 255; j >= 0; j--) {
                unsigned c = g_fine[tid * 256 + j];
                unsigned prev = cum;
                cum += c;
                if (cum >= krem1 && prev < krem1) { g_sel = (unsigned)(tid * 256 + j); g_rem2 = krem1 - prev; }
            }
        }
    }
    fb_bar();
    const unsigned base1 = base0 + (g_sel << 3);
    const unsigned krem2 = g_rem2;

    // level 3: 8 bins of width 1
    for (int i = gtid; i < n4; i += FTOT) {
        float4 v = x[i];
        unsigned u0 = __float_as_uint(v.x) & 0x7FFFFFFFu;
        unsigned u1 = __float_as_uint(v.y) & 0x7FFFFFFFu;
        unsigned u2 = __float_as_uint(v.z) & 0x7FFFFFFFu;
        unsigned u3 = __float_as_uint(v.w) & 0x7FFFFFFFu;
        if (u0 - base1 < 8u) atomicAdd(&g_h2[u0 - base1], 1u);
        if (u1 - base1 < 8u) atomicAdd(&g_h2[u1 - base1], 1u);
        if (u2 - base1 < 8u) atomicAdd(&g_h2[u2 - base1], 1u);
        if (u3 - base1 < 8u) atomicAdd(&g_h2[u3 - base1], 1u);
    }
    for (int g = gtid; g < rem; g += FTOT) {
        unsigned u = __float_as_uint(xs[n4 * 4 + g]) & 0x7FFFFFFFu;
        if (u - base1 < 8u) atomicAdd(&g_h2[u - base1], 1u);
    }
    fb_bar();
    if (blockIdx.x == 0 && tid == 0) {
        unsigned cum = 0;
        for (int j = 7; j >= 0; j--) {
            unsigned prev = cum;
            cum += g_h2[j];
            if (cum >= krem2 && prev < krem2) g_tbits = base1 + (unsigned)j;
        }
    }
    fb_bar();

    // full exact re-mask
    const unsigned tb = g_tbits;
    for (int i = gtid; i < n4; i += FTOT) {
        float4 v = x[i];
        v.x = ((__float_as_uint(v.x) & 0x7FFFFFFFu) >= tb) ? v.x : 0.0f;
        v.y = ((__float_as_uint(v.y) & 0x7FFFFFFFu) >= tb) ? v.y : 0.0f;
        v.z = ((__float_as_uint(v.z) & 0x7FFFFFFFu) >= tb) ? v.z : 0.0f;
        v.w = ((__float_as_uint(v.w) & 0x7FFFFFFFu) >= tb) ? v.w : 0.0f;
        out[i] = v;
    }
    for (int g = gtid; g < rem; g += FTOT) {
        float f = xs[n4 * 4 + g];
        outs[n4 * 4 + g] = ((__float_as_uint(f) & 0x7FFFFFFFu) >= tb) ? f : 0.0f;
    }

    // full clean for next replay (scalars are reset by fix_clean)
    for (unsigned i = gtid; i < NBINS; i += FTOT) g_fine[i] = 0;
    for (int i = gtid; i < NSUP * SUPSTR; i += FTOT) g_superp[i] = 0;
    for (int i = gtid; i < NCOARSE; i += FTOT) g_coarse[i] = 0;
    if (gtid < 8) g_h2[gtid] = 0;
    __syncthreads();
    __threadfence();
    if (tid == 0) {
        if (atomicAdd(&g_fb_cnt, 1u) == FBGRID - 1u) {
            g_fb_cnt = 0; g_fb_sense = 0;
        }
    }
}

// ---------------- K3: fixup keepers + self-clean + scalar reset ------------
__global__ void __launch_bounds__(BLK)
fix_clean(float* __restrict__ out)
{
    const unsigned mode = g_mode;
    const int tid = threadIdx.x;
    const unsigned gtid = blockIdx.x * BLK + tid;
    if (mode == 0u) {
        const unsigned tb = g_tbits;
        const unsigned cnt = g_listcnt;   // <= LISTCAP guaranteed (no overflow)
        for (unsigned j = gtid; j < cnt; j += FIXGRID * BLK) {
            uint2 e = g_list[j];
            unsigned u = e.y & 0x7FFFFFFFu;
            if (u >= tb) out[e.x] = __uint_as_float(e.y);
            unsigned d = u - WLO_N;
            g_fine[d] = 0;
            g_superp[(d >> 8) * SUPSTR] = 0;
        }
    }
    // last block resets scalars (both paths) for the next graph replay
    __syncthreads();
    __threadfence();
    if (tid == 0) {
        if (atomicAdd(&g_done2, 1u) == FIXGRID - 1u) {
            g_A = 0; g_listcnt = 0; g_overflow = 0; g_mode = 0;
            g_done1 = 0; g_done2 = 0;
        }
    }
}

__global__ void copy_all(const float4* __restrict__ x, float4* __restrict__ out, int n4) {
    int idx = blockIdx.x * blockDim.x + threadIdx.x;
    int stride = gridDim.x * blockDim.x;
    for (int i = idx; i < n4; i += stride) out[i] = x[i];
}

extern "C" void kernel_launch(void* const* d_in, const int* in_sizes, int n_in,
                              void* d_out, int out_size) {
    const float* x = (const float*)d_in[0];
    float* out = (float*)d_out;
    int n = in_sizes[0];

    // k = max(1, int(n * (1.0/e))) — bit-exact replication of the Python.
    const double FRACTION = 1.0 / 2.718281828459045235360287;
    long long kll = (long long)((double)n * FRACTION);
    if (kll < 1) kll = 1;

    int n4 = n >> 2;
    int rem = n & 3;

    if (kll >= (long long)n) {
        copy_all<<<GRID, BLK>>>((const float4*)x, (float4*)out, n4);
        return;
    }
    unsigned k = (unsigned)kll;

    fused_p1<<<GRID, BLK>>>((const float4*)x, (float4*)out, n4, rem, k);
    fb_all<<<FBGRID, BLK>>>((const float4*)x, (float4*)out, n4, rem, k);
    fix_clean<<<FIXGRID, BLK>>>(out);
}

// round 16
// speedup vs baseline: 1.0440x; 1.0440x over previous
#include <cuda_runtime.h>
#include <stdint.h>

// ---------------------------------------------------------------------------
// BoltzmannGateSTE: keep top-k (k = int(n/e)) by |x|, zero the rest.
// R16 = R15 stream (43.6us @ 62.6% DRAM, occ 98%) + PDL-hidden tail:
//   K1 fused_p1 (unchanged): stream read -> speculative write; stage window
//      [0.8984375, 0.90234375) elems to list + 2^16 hist + padded supers;
//      LAST block (ticket) verifies AND resolves exact tbits in-kernel.
//   K2 fb_fix (grid 148, PDL): blocks launch during K1's tail drain, warm up,
//      then cudaGridDependencySynchronize(); mode==0 -> scatter-fix keepers +
//      self-clean dirty bins + scalar reset (~3us visible); mode==1 -> cold
//      exact 3-level radix select + re-mask + full clean.
// ---------------------------------------------------------------------------

#define NBINS   (1u << 16)     // fine bins over the window (1 ulp each)
#define NSUP    256            // supers of 256 bins
#define SUPSTR  32             // super stride in uints (128B anti-contention)
#define NCOARSE 4096
#define LISTCAP (1 << 20)      // 1M entries (expected ~70K)
#define CAPB    512            // per-block staging (expected ~59/block)
#define GRID    1184           // 148 SMs * 8 — integral waves
#define BLK     256
#define STRIDE  (GRID * BLK)
#define FBGRID  148
#define WLO_N   0x3F660000u    // bits(0.8984375f)
#define WSPAN_N (1u << 16)
#define WHI_N   (WLO_N + WSPAN_N)   // bits(0.90234375f)

__device__ __align__(16) unsigned g_fine[NBINS];
__device__ unsigned g_superp[NSUP * SUPSTR];   // padded supers
__device__ unsigned g_coarse[NCOARSE];         // fallback only
__device__ unsigned g_h2[8];                   // fallback only
__device__ unsigned g_A;
__device__ unsigned g_listcnt;
__device__ unsigned g_overflow;
__device__ unsigned g_mode;
__device__ unsigned g_tbits;
__device__ unsigned g_sel;         // fallback scan outputs
__device__ unsigned g_rem2;
__device__ unsigned g_done1;       // K1 ticket
__device__ unsigned g_done2;       // K2 ticket
__device__ unsigned g_fb_cnt;      // fallback grid barrier
__device__ volatile unsigned g_fb_sense;
__device__ uint2    g_list[LISTCAP];

// ---------------- K1: fused stream + last-block verify & resolve -----------
__global__ void __launch_bounds__(BLK)
fused_p1(const float4* __restrict__ x, float4* __restrict__ out,
         int n4, int rem, unsigned k)
{
    __shared__ uint2 sbuf[CAPB];          // 4KB staging
    __shared__ unsigned scratch[BLK];     // 1KB reduce/scan
    __shared__ unsigned svar[6];          // 0:scnt 1:sbase 2:sb 3:krem2 4:last 5:mode
    const int tid = threadIdx.x;
    const int gtid = blockIdx.x * BLK + tid;
    const float* xs = (const float*)x;
    float* outs = (float*)out;

    if (tid == 0) svar[0] = 0;
    __syncthreads();

    unsigned cntHi = 0;
#define DO1(f, eidx, odst) { \
    unsigned raw = __float_as_uint(f); \
    unsigned u = raw & 0x7FFFFFFFu; \
    odst = (u >= WHI_N) ? f : 0.0f; \
    cntHi += (u >= WHI_N); \
    if (u - WLO_N < WSPAN_N) { \
        unsigned p = atomicAdd(&svar[0], 1u); \
        if (p < CAPB) { sbuf[p].x = (eidx); sbuf[p].y = raw; } \
    } \
}
#define DO4(vv, fi) { \
    float4 o; \
    unsigned eb = (unsigned)(fi) * 4u; \
    DO1(vv.x, eb + 0u, o.x); \
    DO1(vv.y, eb + 1u, o.y); \
    DO1(vv.z, eb + 2u, o.z); \
    DO1(vv.w, eb + 3u, o.w); \
    __stcs(&out[fi], o); \
}
    {
        int i = gtid;
        for (; i + STRIDE < n4; i += 2 * STRIDE) {
            float4 v0 = __ldcs(&x[i]);
            float4 v1 = __ldcs(&x[i + STRIDE]);
            DO4(v0, i);
            DO4(v1, i + STRIDE);
        }
        for (; i < n4; i += STRIDE) {
            float4 v = __ldcs(&x[i]);
            DO4(v, i);
        }
    }
#undef DO4
#undef DO1
    if (gtid < rem) {   // scalar tail
        float f = xs[n4 * 4 + gtid];
        unsigned raw = __float_as_uint(f);
        unsigned u = raw & 0x7FFFFFFFu;
        cntHi += (u >= WHI_N);
        outs[n4 * 4 + gtid] = (u >= WHI_N) ? f : 0.0f;
        if (u - WLO_N < WSPAN_N) {
            unsigned p = atomicAdd(&svar[0], 1u);
            if (p < CAPB) { sbuf[p].x = (unsigned)(n4 * 4 + gtid); sbuf[p].y = raw; }
        }
    }

    // block-reduce cntHi; reserve list space
    scratch[tid] = cntHi;
    __syncthreads();
    for (int off = BLK / 2; off > 0; off >>= 1) {
        if (tid < off) scratch[tid] += scratch[tid + off];
        __syncthreads();
    }
    if (tid == 0) {
        if (scratch[0]) atomicAdd(&g_A, scratch[0]);
        unsigned c = svar[0];
        if (c > CAPB) { c = CAPB; g_overflow = 1u; }
        unsigned base = atomicAdd(&g_listcnt, c);
        if (base + c > LISTCAP) g_overflow = 1u;
        svar[0] = c;
        svar[1] = base;
    }
    __syncthreads();
    {   // flush staging -> list + fine hist + padded supers
        unsigned c = svar[0], base = svar[1];
        for (unsigned j = tid; j < c; j += BLK) {
            uint2 e = sbuf[j];
            if (base + j < LISTCAP) g_list[base + j] = e;
            unsigned d = (e.y & 0x7FFFFFFFu) - WLO_N;
            atomicAdd(&g_fine[d], 1u);
            atomicAdd(&g_superp[(d >> 8) * SUPSTR], 1u);
        }
    }

    // ---- last block: verify + resolve exact tbits -------------------------
    __syncthreads();
    __threadfence();
    if (tid == 0) svar[4] = (atomicAdd(&g_done1, 1u) == GRID - 1u) ? 1u : 0u;
    __syncthreads();
    if (!svar[4]) return;
    __threadfence();

    if (tid == 0) {
        unsigned A = g_A, cnt = g_listcnt, ov = g_overflow;
        unsigned mode = 1u, krem = 0u;
        if (!ov && A < k && (k - A) <= cnt) { mode = 0u; krem = k - A; }
        g_mode = mode;
        svar[5] = mode;
        svar[3] = krem;
    }
    __syncthreads();
    if (svar[5]) return;            // fallback kernel will handle it
    const unsigned krem = svar[3];

    // scan 256 supers (descending rank)
    unsigned c = g_superp[tid * SUPSTR];
    scratch[tid] = c;
    __syncthreads();
    for (int off = 1; off < BLK; off <<= 1) {
        unsigned add = (tid + off < BLK) ? scratch[tid + off] : 0u;
        __syncthreads();
        scratch[tid] += add;
        __syncthreads();
    }
    {
        unsigned above = (tid < BLK - 1) ? scratch[tid + 1] : 0u;
        if (above < krem && above + c >= krem) { svar[2] = (unsigned)tid; svar[3] = krem - above; }
    }
    __syncthreads();
    const unsigned sb = svar[2], krem2 = svar[3];

    // scan the 256 fine bins of super sb
    unsigned c2 = g_fine[sb * 256u + tid];
    __syncthreads();
    scratch[tid] = c2;
    __syncthreads();
    for (int off = 1; off < BLK; off <<= 1) {
        unsigned add = (tid + off < BLK) ? scratch[tid + off] : 0u;
        __syncthreads();
        scratch[tid] += add;
        __syncthreads();
    }
    {
        unsigned above = (tid < BLK - 1) ? scratch[tid + 1] : 0u;
        if (above < krem2 && above + c2 >= krem2)
            g_tbits = WLO_N + sb * 256u + (unsigned)tid;
    }
}

// ---------------- K2: PDL tail — fixup+clean (hot) / full fallback (cold) --
__device__ __forceinline__ void fb_bar() {
    __syncthreads();
    if (threadIdx.x == 0) {
        unsigned s = g_fb_sense ^ 1u;
        __threadfence();
        if (atomicAdd(&g_fb_cnt, 1u) == FBGRID - 1u) {
            g_fb_cnt = 0u;
            __threadfence();
            g_fb_sense = s;
        } else {
            while (g_fb_sense != s) __nanosleep(64);
            __threadfence();
        }
    }
    __syncthreads();
}

__global__ void __launch_bounds__(BLK)
fb_fix(const float4* __restrict__ x, float4* __restrict__ out,
       int n4, int rem, unsigned k)
{
    // Blocks may start while fused_p1 drains (PDL). Wait for its completion
    // + memory visibility before reading any of its results.
    cudaGridDependencySynchronize();

    __shared__ unsigned scratch[BLK];
    const int tid = threadIdx.x;
    const int gtid = blockIdx.x * BLK + tid;
    const int FTOT = FBGRID * BLK;
    const float* xs = (const float*)x;
    float* outs = (float*)out;
    const unsigned mode = g_mode;

    if (mode == 0u) {
        // ---- HOT: fixup keepers + self-clean dirtied bins -----------------
        const unsigned tb = g_tbits;
        const unsigned cnt = g_listcnt;   // <= LISTCAP guaranteed (no overflow)
        for (unsigned j = (unsigned)gtid; j < cnt; j += FTOT) {
            uint2 e = g_list[j];
            unsigned u = e.y & 0x7FFFFFFFu;
            if (u >= tb) outs[e.x] = __uint_as_float(e.y);
            unsigned d = u - WLO_N;
            g_fine[d] = 0;
            g_superp[(d >> 8) * SUPSTR] = 0;
        }
        __syncthreads();
        __threadfence();
        if (tid == 0) {
            if (atomicAdd(&g_done2, 1u) == FBGRID - 1u) {
                g_A = 0; g_listcnt = 0; g_overflow = 0; g_mode = 0;
                g_done1 = 0; g_done2 = 0;
            }
        }
        return;
    }

    // =============== COLD: exact 3-level radix select ======================
    for (unsigned i = gtid; i < NBINS; i += FTOT) g_fine[i] = 0;
    for (int i = gtid; i < NSUP * SUPSTR; i += FTOT) g_superp[i] = 0;
    if (gtid < 8) g_h2[gtid] = 0;
    fb_bar();

    // level 1: coarse hist (4096 bins of 2^19)
    for (int i = gtid; i < n4; i += FTOT) {
        float4 v = x[i];
        atomicAdd(&g_coarse[(__float_as_uint(v.x) & 0x7FFFFFFFu) >> 19], 1u);
        atomicAdd(&g_coarse[(__float_as_uint(v.y) & 0x7FFFFFFFu) >> 19], 1u);
        atomicAdd(&g_coarse[(__float_as_uint(v.z) & 0x7FFFFFFFu) >> 19], 1u);
        atomicAdd(&g_coarse[(__float_as_uint(v.w) & 0x7FFFFFFFu) >> 19], 1u);
    }
    for (int g = gtid; g < rem; g += FTOT)
        atomicAdd(&g_coarse[(__float_as_uint(xs[n4 * 4 + g]) & 0x7FFFFFFFu) >> 19], 1u);
    fb_bar();

    if (blockIdx.x == 0) {   // scan 4096: 16 per thread
        unsigned c[16], sum = 0;
        #pragma unroll
        for (int j = 0; j < 16; j++) { c[j] = g_coarse[tid * 16 + j]; sum += c[j]; }
        scratch[tid] = sum;
        __syncthreads();
        for (int off = 1; off < BLK; off <<= 1) {
            unsigned add = (tid + off < BLK) ? scratch[tid + off] : 0u;
            __syncthreads();
            scratch[tid] += add;
            __syncthreads();
        }
        unsigned cum = (tid < BLK - 1) ? scratch[tid + 1] : 0u;
        #pragma unroll
        for (int j = 15; j >= 0; j--) {
            unsigned prev = cum;
            cum += c[j];
            if (cum >= k && prev < k) { g_sel = (unsigned)(tid * 16 + j); g_rem2 = k - prev; }
        }
    }
    fb_bar();
    const unsigned base0 = g_sel << 19;
    const unsigned krem1 = g_rem2;

    // level 2: 2^16 bins of width 8
    for (int i = gtid; i < n4; i += FTOT) {
        float4 v = x[i];
        unsigned u0 = __float_as_uint(v.x) & 0x7FFFFFFFu;
        unsigned u1 = __float_as_uint(v.y) & 0x7FFFFFFFu;
        unsigned u2 = __float_as_uint(v.z) & 0x7FFFFFFFu;
        unsigned u3 = __float_as_uint(v.w) & 0x7FFFFFFFu;
        if (u0 - base0 < (1u << 19)) atomicAdd(&g_fine[(u0 - base0) >> 3], 1u);
        if (u1 - base0 < (1u << 19)) atomicAdd(&g_fine[(u1 - base0) >> 3], 1u);
        if (u2 - base0 < (1u << 19)) atomicAdd(&g_fine[(u2 - base0) >> 3], 1u);
        if (u3 - base0 < (1u << 19)) atomicAdd(&g_fine[(u3 - base0) >> 3], 1u);
    }
    for (int g = gtid; g < rem; g += FTOT) {
        unsigned u = __float_as_uint(xs[n4 * 4 + g]) & 0x7FFFFFFFu;
        if (u - base0 < (1u << 19)) atomicAdd(&g_fine[(u - base0) >> 3], 1u);
    }
    fb_bar();

    if (blockIdx.x == 0) {   // scan 65536: 256 per thread (cold path)
        unsigned sum = 0;
        for (int j = 0; j < 256; j++) sum += g_fine[tid * 256 + j];
        scratch[tid] = sum;
        __syncthreads();
        for (int off = 1; off < BLK; off <<= 1) {
            unsigned add = (tid + off < BLK) ? scratch[tid + off] : 0u;
            __syncthreads();
            scratch[tid] += add;
            __syncthreads();
        }
        unsigned above = (tid < BLK - 1) ? scratch[tid + 1] : 0u;
        if (above < krem1 && above + sum >= krem1) {
            unsigned cum = above;
            for (int j = 255; j >= 0; j--) {
                unsigned c = g_fine[tid * 256 + j];
                unsigned prev = cum;
                cum += c;
                if (cum >= krem1 && prev < krem1) { g_sel = (unsigned)(tid * 256 + j); g_rem2 = krem1 - prev; }
            }
        }
    }
    fb_bar();
    const unsigned base1 = base0 + (g_sel << 3);
    const unsigned krem2 = g_rem2;

    // level 3: 8 bins of width 1
    for (int i = gtid; i < n4; i += FTOT) {
        float4 v = x[i];
        unsigned u0 = __float_as_uint(v.x) & 0x7FFFFFFFu;
        unsigned u1 = __float_as_uint(v.y) & 0x7FFFFFFFu;
        unsigned u2 = __float_as_uint(v.z) & 0x7FFFFFFFu;
        unsigned u3 = __float_as_uint(v.w) & 0x7FFFFFFFu;
        if (u0 - base1 < 8u) atomicAdd(&g_h2[u0 - base1], 1u);
        if (u1 - base1 < 8u) atomicAdd(&g_h2[u1 - base1], 1u);
        if (u2 - base1 < 8u) atomicAdd(&g_h2[u2 - base1], 1u);
        if (u3 - base1 < 8u) atomicAdd(&g_h2[u3 - base1], 1u);
    }
    for (int g = gtid; g < rem; g += FTOT) {
        unsigned u = __float_as_uint(xs[n4 * 4 + g]) & 0x7FFFFFFFu;
        if (u - base1 < 8u) atomicAdd(&g_h2[u - base1], 1u);
    }
    fb_bar();
    if (blockIdx.x == 0 && tid == 0) {
        unsigned cum = 0;
        for (int j = 7; j >= 0; j--) {
            unsigned prev = cum;
            cum += g_h2[j];
            if (cum >= krem2 && prev < krem2) g_tbits = base1 + (unsigned)j;
        }
    }
    fb_bar();

    // full exact re-mask
    const unsigned tb = g_tbits;
    for (int i = gtid; i < n4; i += FTOT) {
        float4 v = x[i];
        v.x = ((__float_as_uint(v.x) & 0x7FFFFFFFu) >= tb) ? v.x : 0.0f;
        v.y = ((__float_as_uint(v.y) & 0x7FFFFFFFu) >= tb) ? v.y : 0.0f;
        v.z = ((__float_as_uint(v.z) & 0x7FFFFFFFu) >= tb) ? v.z : 0.0f;
        v.w = ((__float_as_uint(v.w) & 0x7FFFFFFFu) >= tb) ? v.w : 0.0f;
        out[i] = v;
    }
    for (int g = gtid; g < rem; g += FTOT) {
        float f = xs[n4 * 4 + g];
        outs[n4 * 4 + g] = ((__float_as_uint(f) & 0x7FFFFFFFu) >= tb) ? f : 0.0f;
    }

    // full clean for next replay
    for (unsigned i = gtid; i < NBINS; i += FTOT) g_fine[i] = 0;
    for (int i = gtid; i < NSUP * SUPSTR; i += FTOT) g_superp[i] = 0;
    for (int i = gtid; i < NCOARSE; i += FTOT) g_coarse[i] = 0;
    if (gtid < 8) g_h2[gtid] = 0;
    __syncthreads();
    __threadfence();
    if (tid == 0) {
        if (atomicAdd(&g_done2, 1u) == FBGRID - 1u) {
            g_fb_cnt = 0; g_fb_sense = 0;
            g_A = 0; g_listcnt = 0; g_overflow = 0; g_mode = 0;
            g_done1 = 0; g_done2 = 0;
        }
    }
}

__global__ void copy_all(const float4* __restrict__ x, float4* __restrict__ out, int n4) {
    int idx = blockIdx.x * blockDim.x + threadIdx.x;
    int stride = gridDim.x * blockDim.x;
    for (int i = idx; i < n4; i += stride) out[i] = x[i];
}

extern "C" void kernel_launch(void* const* d_in, const int* in_sizes, int n_in,
                              void* d_out, int out_size) {
    const float* x = (const float*)d_in[0];
    float* out = (float*)d_out;
    int n = in_sizes[0];

    // k = max(1, int(n * (1.0/e))) — bit-exact replication of the Python.
    const double FRACTION = 1.0 / 2.718281828459045235360287;
    long long kll = (long long)((double)n * FRACTION);
    if (kll < 1) kll = 1;

    int n4 = n >> 2;
    int rem = n & 3;

    if (kll >= (long long)n) {
        copy_all<<<GRID, BLK>>>((const float4*)x, (float4*)out, n4);
        return;
    }
    unsigned k = (unsigned)kll;

    fused_p1<<<GRID, BLK>>>((const float4*)x, (float4*)out, n4, rem, k);

    // PDL launch of the tail kernel: blocks spin up while fused_p1 drains,
    // then cudaGridDependencySynchronize() gates on its completion.
    {
        cudaLaunchConfig_t cfg = {};
        cfg.gridDim = dim3(FBGRID);
        cfg.blockDim = dim3(BLK);
        cfg.dynamicSmemBytes = 0;
        cfg.stream = 0;
        cudaLaunchAttribute attr[1];
        attr[0].id = cudaLaunchAttributeProgrammaticStreamSerialization;
        attr[0].val.programmaticStreamSerializationAllowed = 1;
        cfg.attrs = attr;
        cfg.numAttrs = 1;
        cudaError_t err = cudaLaunchKernelEx(&cfg, fb_fix,
                                             (const float4*)x, (float4*)out,
                                             n4, rem, k);
        if (err != cudaSuccess) {
            // PDL unsupported in this context: plain serialized launch.
            fb_fix<<<FBGRID, BLK>>>((const float4*)x, (float4*)out, n4, rem, k);
        }
    }
}

// round 17
// speedup vs baseline: 1.0838x; 1.0382x over previous
#include <cuda_runtime.h>
#include <stdint.h>

// ---------------------------------------------------------------------------
// BoltzmannGateSTE: keep top-k (k = int(n/e)) by |x|, zero the rest.
// R17 = R16 (57.5us) with a leaner tail:
//   - window halved to 2^15 ulps, re-centered: [0.89941, 0.90234), k-th |x|
//     = 0.9005 +- 0.00016 -> 7-11 sigma margins; ~35K staged elems.
//   - fb_fix hot path: coalesced linear zero of hist scratch (not scattered),
//     list loop writes keepers only.
//   K1 fused_p1: stream read -> speculative write; stage window elems to
//      list + 2^15 hist + padded supers; LAST block verifies + resolves tbits.
//   K2 fb_fix (PDL): hot -> fixup keepers + linear clean + scalar reset;
//      cold -> exact 3-level radix select + re-mask + full clean.
// ---------------------------------------------------------------------------

#define NBINS   (1u << 15)     // fine bins over the window (1 ulp each)
#define NSUP    128            // supers of 256 bins
#define SUPSTR  32             // super stride in uints (128B anti-contention)
#define NCOARSE 4096
#define LISTCAP (1 << 20)      // 1M entries (expected ~35K)
#define CAPB    512            // per-block staging (expected ~30/block)
#define GRID    1184           // 148 SMs * 8 — integral waves
#define BLK     256
#define STRIDE  (GRID * BLK)
#define FBGRID  148
#define WLO_N   0x3F668000u    // bits(0.899414f)
#define WSPAN_N (1u << 15)
#define WHI_N   (WLO_N + WSPAN_N)   // bits(0.902344f)

__device__ __align__(16) unsigned g_fine[NBINS];
__device__ unsigned g_superp[NSUP * SUPSTR];   // padded supers
__device__ unsigned g_coarse[NCOARSE];         // fallback only
__device__ unsigned g_h2[16];                  // fallback only
__device__ unsigned g_A;
__device__ unsigned g_listcnt;
__device__ unsigned g_overflow;
__device__ unsigned g_mode;
__device__ unsigned g_tbits;
__device__ unsigned g_sel;         // fallback scan outputs
__device__ unsigned g_rem2;
__device__ unsigned g_done1;       // K1 ticket
__device__ unsigned g_done2;       // K2 ticket
__device__ unsigned g_fb_cnt;      // fallback grid barrier
__device__ volatile unsigned g_fb_sense;
__device__ uint2    g_list[LISTCAP];

// ---------------- K1: fused stream + last-block verify & resolve -----------
__global__ void __launch_bounds__(BLK)
fused_p1(const float4* __restrict__ x, float4* __restrict__ out,
         int n4, int rem, unsigned k)
{
    __shared__ uint2 sbuf[CAPB];          // 4KB staging
    __shared__ unsigned scratch[BLK];     // 1KB reduce/scan
    __shared__ unsigned svar[6];          // 0:scnt 1:sbase 2:sb 3:krem2 4:last 5:mode
    const int tid = threadIdx.x;
    const int gtid = blockIdx.x * BLK + tid;
    const float* xs = (const float*)x;
    float* outs = (float*)out;

    if (tid == 0) svar[0] = 0;
    __syncthreads();

    unsigned cntHi = 0;
#define DO1(f, eidx, odst) { \
    unsigned raw = __float_as_uint(f); \
    unsigned u = raw & 0x7FFFFFFFu; \
    odst = (u >= WHI_N) ? f : 0.0f; \
    cntHi += (u >= WHI_N); \
    if (u - WLO_N < WSPAN_N) { \
        unsigned p = atomicAdd(&svar[0], 1u); \
        if (p < CAPB) { sbuf[p].x = (eidx); sbuf[p].y = raw; } \
    } \
}
#define DO4(vv, fi) { \
    float4 o; \
    unsigned eb = (unsigned)(fi) * 4u; \
    DO1(vv.x, eb + 0u, o.x); \
    DO1(vv.y, eb + 1u, o.y); \
    DO1(vv.z, eb + 2u, o.z); \
    DO1(vv.w, eb + 3u, o.w); \
    __stcs(&out[fi], o); \
}
    {
        int i = gtid;
        for (; i + STRIDE < n4; i += 2 * STRIDE) {
            float4 v0 = __ldcs(&x[i]);
            float4 v1 = __ldcs(&x[i + STRIDE]);
            DO4(v0, i);
            DO4(v1, i + STRIDE);
        }
        for (; i < n4; i += STRIDE) {
            float4 v = __ldcs(&x[i]);
            DO4(v, i);
        }
    }
#undef DO4
#undef DO1
    if (gtid < rem) {   // scalar tail
        float f = xs[n4 * 4 + gtid];
        unsigned raw = __float_as_uint(f);
        unsigned u = raw & 0x7FFFFFFFu;
        cntHi += (u >= WHI_N);
        outs[n4 * 4 + gtid] = (u >= WHI_N) ? f : 0.0f;
        if (u - WLO_N < WSPAN_N) {
            unsigned p = atomicAdd(&svar[0], 1u);
            if (p < CAPB) { sbuf[p].x = (unsigned)(n4 * 4 + gtid); sbuf[p].y = raw; }
        }
    }

    // block-reduce cntHi; reserve list space
    scratch[tid] = cntHi;
    __syncthreads();
    for (int off = BLK / 2; off > 0; off >>= 1) {
        if (tid < off) scratch[tid] += scratch[tid + off];
        __syncthreads();
    }
    if (tid == 0) {
        if (scratch[0]) atomicAdd(&g_A, scratch[0]);
        unsigned c = svar[0];
        if (c > CAPB) { c = CAPB; g_overflow = 1u; }
        unsigned base = atomicAdd(&g_listcnt, c);
        if (base + c > LISTCAP) g_overflow = 1u;
        svar[0] = c;
        svar[1] = base;
    }
    __syncthreads();
    {   // flush staging -> list + fine hist + padded supers
        unsigned c = svar[0], base = svar[1];
        for (unsigned j = tid; j < c; j += BLK) {
            uint2 e = sbuf[j];
            if (base + j < LISTCAP) g_list[base + j] = e;
            unsigned d = (e.y & 0x7FFFFFFFu) - WLO_N;
            atomicAdd(&g_fine[d], 1u);
            atomicAdd(&g_superp[(d >> 8) * SUPSTR], 1u);
        }
    }

    // ---- last block: verify + resolve exact tbits -------------------------
    __syncthreads();
    __threadfence();
    if (tid == 0) svar[4] = (atomicAdd(&g_done1, 1u) == GRID - 1u) ? 1u : 0u;
    __syncthreads();
    if (!svar[4]) return;
    __threadfence();

    if (tid == 0) {
        unsigned A = g_A, cnt = g_listcnt, ov = g_overflow;
        unsigned mode = 1u, krem = 0u;
        if (!ov && A < k && (k - A) <= cnt) { mode = 0u; krem = k - A; }
        g_mode = mode;
        svar[5] = mode;
        svar[3] = krem;
    }
    __syncthreads();
    if (svar[5]) return;            // fallback kernel will handle it
    const unsigned krem = svar[3];

    // scan 128 supers (descending rank); threads 128..255 contribute zero
    unsigned c = (tid < NSUP) ? g_superp[tid * SUPSTR] : 0u;
    scratch[tid] = c;
    __syncthreads();
    for (int off = 1; off < BLK; off <<= 1) {
        unsigned add = (tid + off < BLK) ? scratch[tid + off] : 0u;
        __syncthreads();
        scratch[tid] += add;
        __syncthreads();
    }
    {
        unsigned above = (tid < BLK - 1) ? scratch[tid + 1] : 0u;
        if (tid < NSUP && above < krem && above + c >= krem) {
            svar[2] = (unsigned)tid; svar[3] = krem - above;
        }
    }
    __syncthreads();
    const unsigned sb = svar[2], krem2 = svar[3];

    // scan the 256 fine bins of super sb
    unsigned c2 = g_fine[sb * 256u + tid];
    __syncthreads();
    scratch[tid] = c2;
    __syncthreads();
    for (int off = 1; off < BLK; off <<= 1) {
        unsigned add = (tid + off < BLK) ? scratch[tid + off] : 0u;
        __syncthreads();
        scratch[tid] += add;
        __syncthreads();
    }
    {
        unsigned above = (tid < BLK - 1) ? scratch[tid + 1] : 0u;
        if (above < krem2 && above + c2 >= krem2)
            g_tbits = WLO_N + sb * 256u + (unsigned)tid;
    }
}

// ---------------- K2: PDL tail — fixup+clean (hot) / full fallback (cold) --
__device__ __forceinline__ void fb_bar() {
    __syncthreads();
    if (threadIdx.x == 0) {
        unsigned s = g_fb_sense ^ 1u;
        __threadfence();
        if (atomicAdd(&g_fb_cnt, 1u) == FBGRID - 1u) {
            g_fb_cnt = 0u;
            __threadfence();
            g_fb_sense = s;
        } else {
            while (g_fb_sense != s) __nanosleep(64);
            __threadfence();
        }
    }
    __syncthreads();
}

__global__ void __launch_bounds__(BLK)
fb_fix(const float4* __restrict__ x, float4* __restrict__ out,
       int n4, int rem, unsigned k)
{
    // Blocks may start while fused_p1 drains (PDL). Wait for its completion
    // + memory visibility before reading any of its results.
    cudaGridDependencySynchronize();

    __shared__ unsigned scratch[BLK];
    const int tid = threadIdx.x;
    const int gtid = blockIdx.x * BLK + tid;
    const int FTOT = FBGRID * BLK;
    const float* xs = (const float*)x;
    float* outs = (float*)out;
    const unsigned mode = g_mode;

    if (mode == 0u) {
        // ---- HOT: fixup keepers (scattered, small) ------------------------
        const unsigned tb = g_tbits;
        const unsigned cnt = g_listcnt;   // <= LISTCAP guaranteed (no overflow)
        for (unsigned j = (unsigned)gtid; j < cnt; j += FTOT) {
            uint2 e = g_list[j];
            unsigned u = e.y & 0x7FFFFFFFu;
            if (u >= tb) outs[e.x] = __uint_as_float(e.y);
        }
        // ---- linear clean of hist scratch (coalesced) ---------------------
        {
            uint4 z = make_uint4(0, 0, 0, 0);
            uint4* f4 = (uint4*)g_fine;
            for (unsigned i = gtid; i < NBINS / 4; i += FTOT) f4[i] = z;
            uint4* s4 = (uint4*)g_superp;
            for (int i = gtid; i < NSUP * SUPSTR / 4; i += FTOT) s4[i] = z;
        }
        __syncthreads();
        __threadfence();
        if (tid == 0) {
            if (atomicAdd(&g_done2, 1u) == FBGRID - 1u) {
                g_A = 0; g_listcnt = 0; g_overflow = 0; g_mode = 0;
                g_done1 = 0; g_done2 = 0;
            }
        }
        return;
    }

    // =============== COLD: exact 3-level radix select ======================
    for (unsigned i = gtid; i < NBINS; i += FTOT) g_fine[i] = 0;
    for (int i = gtid; i < NSUP * SUPSTR; i += FTOT) g_superp[i] = 0;
    if (gtid < 16) g_h2[gtid] = 0;
    fb_bar();

    // level 1: coarse hist (4096 bins of 2^19)
    for (int i = gtid; i < n4; i += FTOT) {
        float4 v = x[i];
        atomicAdd(&g_coarse[(__float_as_uint(v.x) & 0x7FFFFFFFu) >> 19], 1u);
        atomicAdd(&g_coarse[(__float_as_uint(v.y) & 0x7FFFFFFFu) >> 19], 1u);
        atomicAdd(&g_coarse[(__float_as_uint(v.z) & 0x7FFFFFFFu) >> 19], 1u);
        atomicAdd(&g_coarse[(__float_as_uint(v.w) & 0x7FFFFFFFu) >> 19], 1u);
    }
    for (int g = gtid; g < rem; g += FTOT)
        atomicAdd(&g_coarse[(__float_as_uint(xs[n4 * 4 + g]) & 0x7FFFFFFFu) >> 19], 1u);
    fb_bar();

    if (blockIdx.x == 0) {   // scan 4096: 16 per thread
        unsigned c[16], sum = 0;
        #pragma unroll
        for (int j = 0; j < 16; j++) { c[j] = g_coarse[tid * 16 + j]; sum += c[j]; }
        scratch[tid] = sum;
        __syncthreads();
        for (int off = 1; off < BLK; off <<= 1) {
            unsigned add = (tid + off < BLK) ? scratch[tid + off] : 0u;
            __syncthreads();
            scratch[tid] += add;
            __syncthreads();
        }
        unsigned cum = (tid < BLK - 1) ? scratch[tid + 1] : 0u;
        #pragma unroll
        for (int j = 15; j >= 0; j--) {
            unsigned prev = cum;
            cum += c[j];
            if (cum >= k && prev < k) { g_sel = (unsigned)(tid * 16 + j); g_rem2 = k - prev; }
        }
    }
    fb_bar();
    const unsigned base0 = g_sel << 19;
    const unsigned krem1 = g_rem2;

    // level 2: 2^15 bins of width 16 over [base0, base0 + 2^19)
    for (int i = gtid; i < n4; i += FTOT) {
        float4 v = x[i];
        unsigned u0 = __float_as_uint(v.x) & 0x7FFFFFFFu;
        unsigned u1 = __float_as_uint(v.y) & 0x7FFFFFFFu;
        unsigned u2 = __float_as_uint(v.z) & 0x7FFFFFFFu;
        unsigned u3 = __float_as_uint(v.w) & 0x7FFFFFFFu;
        if (u0 - base0 < (1u << 19)) atomicAdd(&g_fine[(u0 - base0) >> 4], 1u);
        if (u1 - base0 < (1u << 19)) atomicAdd(&g_fine[(u1 - base0) >> 4], 1u);
        if (u2 - base0 < (1u << 19)) atomicAdd(&g_fine[(u2 - base0) >> 4], 1u);
        if (u3 - base0 < (1u << 19)) atomicAdd(&g_fine[(u3 - base0) >> 4], 1u);
    }
    for (int g = gtid; g < rem; g += FTOT) {
        unsigned u = __float_as_uint(xs[n4 * 4 + g]) & 0x7FFFFFFFu;
        if (u - base0 < (1u << 19)) atomicAdd(&g_fine[(u - base0) >> 4], 1u);
    }
    fb_bar();

    if (blockIdx.x == 0) {   // scan 32768: 128 per thread (cold path)
        unsigned sum = 0;
        for (int j = 0; j < 128; j++) sum += g_fine[tid * 128 + j];
        scratch[tid] = sum;
        __syncthreads();
        for (int off = 1; off < BLK; off <<= 1) {
            unsigned add = (tid + off < BLK) ? scratch[tid + off] : 0u;
            __syncthreads();
            scratch[tid] += add;
            __syncthreads();
        }
        unsigned above = (tid < BLK - 1) ? scratch[tid + 1] : 0u;
        if (above < krem1 && above + sum >= krem1) {
            unsigned cum = above;
            for (int j = 127; j >= 0; j--) {
                unsigned c = g_fine[tid * 128 + j];
                unsigned prev = cum;
                cum += c;
                if (cum >= krem1 && prev < krem1) { g_sel = (unsigned)(tid * 128 + j); g_rem2 = krem1 - prev; }
            }
        }
    }
    fb_bar();
    const unsigned base1 = base0 + (g_sel << 4);
    const unsigned krem2 = g_rem2;

    // level 3: 16 bins of width 1
    for (int i = gtid; i < n4; i += FTOT) {
        float4 v = x[i];
        unsigned u0 = __float_as_uint(v.x) & 0x7FFFFFFFu;
        unsigned u1 = __float_as_uint(v.y) & 0x7FFFFFFFu;
        unsigned u2 = __float_as_uint(v.z) & 0x7FFFFFFFu;
        unsigned u3 = __float_as_uint(v.w) & 0x7FFFFFFFu;
        if (u0 - base1 < 16u) atomicAdd(&g_h2[u0 - base1], 1u);
        if (u1 - base1 < 16u) atomicAdd(&g_h2[u1 - base1], 1u);
        if (u2 - base1 < 16u) atomicAdd(&g_h2[u2 - base1], 1u);
        if (u3 - base1 < 16u) atomicAdd(&g_h2[u3 - base1], 1u);
    }
    for (int g = gtid; g < rem; g += FTOT) {
        unsigned u = __float_as_uint(xs[n4 * 4 + g]) & 0x7FFFFFFFu;
        if (u - base1 < 16u) atomicAdd(&g_h2[u - base1], 1u);
    }
    fb_bar();
    if (blockIdx.x == 0 && tid == 0) {
        unsigned cum = 0;
        for (int j = 15; j >= 0; j--) {
            unsigned prev = cum;
            cum += g_h2[j];
            if (cum >= krem2 && prev < krem2) g_tbits = base1 + (unsigned)j;
        }
    }
    fb_bar();

    // full exact re-mask
    const unsigned tb = g_tbits;
    for (int i = gtid; i < n4; i += FTOT) {
        float4 v = x[i];
        v.x = ((__float_as_uint(v.x) & 0x7FFFFFFFu) >= tb) ? v.x : 0.0f;
        v.y = ((__float_as_uint(v.y) & 0x7FFFFFFFu) >= tb) ? v.y : 0.0f;
        v.z = ((__float_as_uint(v.z) & 0x7FFFFFFFu) >= tb) ? v.z : 0.0f;
        v.w = ((__float_as_uint(v.w) & 0x7FFFFFFFu) >= tb) ? v.w : 0.0f;
        out[i] = v;
    }
    for (int g = gtid; g < rem; g += FTOT) {
        float f = xs[n4 * 4 + g];
        outs[n4 * 4 + g] = ((__float_as_uint(f) & 0x7FFFFFFFu) >= tb) ? f : 0.0f;
    }

    // full clean for next replay
    for (unsigned i = gtid; i < NBINS; i += FTOT) g_fine[i] = 0;
    for (int i = gtid; i < NSUP * SUPSTR; i += FTOT) g_superp[i] = 0;
    for (int i = gtid; i < NCOARSE; i += FTOT) g_coarse[i] = 0;
    if (gtid < 16) g_h2[gtid] = 0;
    __syncthreads();
    __threadfence();
    if (tid == 0) {
        if (atomicAdd(&g_done2, 1u) == FBGRID - 1u) {
            g_fb_cnt = 0; g_fb_sense = 0;
            g_A = 0; g_listcnt = 0; g_overflow = 0; g_mode = 0;
            g_done1 = 0; g_done2 = 0;
        }
    }
}

__global__ void copy_all(const float4* __restrict__ x, float4* __restrict__ out, int n4) {
    int idx = blockIdx.x * blockDim.x + threadIdx.x;
    int stride = gridDim.x * blockDim.x;
    for (int i = idx; i < n4; i += stride) out[i] = x[i];
}

extern "C" void kernel_launch(void* const* d_in, const int* in_sizes, int n_in,
                              void* d_out, int out_size) {
    const float* x = (const float*)d_in[0];
    float* out = (float*)d_out;
    int n = in_sizes[0];

    // k = max(1, int(n * (1.0/e))) — bit-exact replication of the Python.
    const double FRACTION = 1.0 / 2.718281828459045235360287;
    long long kll = (long long)((double)n * FRACTION);
    if (kll < 1) kll = 1;

    int n4 = n >> 2;
    int rem = n & 3;

    if (kll >= (long long)n) {
        copy_all<<<GRID, BLK>>>((const float4*)x, (float4*)out, n4);
        return;
    }
    unsigned k = (unsigned)kll;

    fused_p1<<<GRID, BLK>>>((const float4*)x, (float4*)out, n4, rem, k);

    // PDL launch of the tail kernel: blocks spin up while fused_p1 drains,
    // then cudaGridDependencySynchronize() gates on its completion.
    {
        cudaLaunchConfig_t cfg = {};
        cfg.gridDim = dim3(FBGRID);
        cfg.blockDim = dim3(BLK);
        cfg.dynamicSmemBytes = 0;
        cfg.stream = 0;
        cudaLaunchAttribute attr[1];
        attr[0].id = cudaLaunchAttributeProgrammaticStreamSerialization;
        attr[0].val.programmaticStreamSerializationAllowed = 1;
        cfg.attrs = attr;
        cfg.numAttrs = 1;
        cudaError_t err = cudaLaunchKernelEx(&cfg, fb_fix,
                                             (const float4*)x, (float4*)out,
                                             n4, rem, k);
        if (err != cudaSuccess) {
            // PDL unsupported in this context: plain serialized launch.
            fb_fix<<<FBGRID, BLK>>>((const float4*)x, (float4*)out, n4, rem, k);
        }
    }
}